// round 9
// baseline (speedup 1.0000x reference)
#include <cuda_runtime.h>
#include <cstdint>

#define TLEN   8192
#define BATCH  128
#define NS     128
#define EMITN  64
#define NT     288   // 2 batch-groups x 4 compute warps + 1 shared relay warp

// ---- packed f32x2 helpers (sm_103a) ----
__device__ __forceinline__ void fma2(unsigned long long& d, unsigned long long a, unsigned long long b) {
    asm("fma.rn.f32x2 %0, %1, %2, %0;" : "+l"(d) : "l"(a), "l"(b));
}
__device__ __forceinline__ unsigned long long mul2(unsigned long long a, unsigned long long b) {
    unsigned long long d;
    asm("mul.rn.f32x2 %0, %1, %2;" : "=l"(d) : "l"(a), "l"(b));
    return d;
}
__device__ __forceinline__ unsigned long long padd(unsigned long long a, unsigned long long b) {
    unsigned long long d;
    asm("add.rn.f32x2 %0, %1, %2;" : "=l"(d) : "l"(a), "l"(b));
    return d;
}
__device__ __forceinline__ unsigned long long pk(float lo, float hi) {
    unsigned long long r;
    asm("mov.b64 %0, {%1, %2};" : "=l"(r) : "f"(lo), "f"(hi));
    return r;
}
__device__ __forceinline__ float hsum2(unsigned long long v) {
    float lo, hi;
    asm("mov.b64 {%0, %1}, %2;" : "=f"(lo), "=f"(hi) : "l"(v));
    return lo + hi;
}

__global__ __launch_bounds__(NT, 1)
void hmm_forward_kernel(const float* __restrict__ inputs,
                        const float* __restrict__ Ivec,
                        const float* __restrict__ Amat,
                        const float* __restrict__ Bmat,
                        float* __restrict__ out)
{
    __shared__ float Bsh[EMITN * NS];                 // 32 KB (shared: same B)
    __shared__ unsigned char obs_sm[2][TLEN];         // 16 KB (per batch-group)
    __shared__ __align__(16) float ubuf[2][2][NS];    // [group][buf][state]
    __shared__ __align__(16) float zs1[2][2][8];      // relay partials per group
    __shared__ float sc_sm[2][2];                     // pow2 scale per group
    __shared__ __align__(16) float znext[2][4];
    __shared__ __align__(16) float zvs[2][4];
    __shared__ int stot_sm[2];

    const int tid  = threadIdx.x;
    const int lane = tid & 31;
    const int w    = tid >> 5;            // 0..8
    const bool isCompute = (tid < 256);
    const int g    = (tid >> 7) & 1;      // batch group (compute threads)
    const int s    = tid & 127;           // state
    const int wg   = w & 3;               // warp index within group

    // ---- prologue: B into smem ----
    for (int i = tid; i < EMITN * NS; i += NT) Bsh[i] = Bmat[i];

    // ---- prologue: one-hot -> obs indices for both batches ----
    #pragma unroll
    for (int bi = 0; bi < 2; bi++) {
        const float* xin = inputs + ((size_t)(2 * blockIdx.x + bi)) * TLEN * EMITN;
        for (int t = tid; t < TLEN; t += NT) {
            const float4* r = (const float4*)(xin + (size_t)t * EMITN);
            float idx = 0.0f;
            #pragma unroll
            for (int j = 0; j < 16; j++) {
                float4 v = r[j];
                idx = fmaf((float)(4 * j + 0), v.x, idx);
                idx = fmaf((float)(4 * j + 1), v.y, idx);
                idx = fmaf((float)(4 * j + 2), v.z, idx);
                idx = fmaf((float)(4 * j + 3), v.w, idx);
            }
            obs_sm[bi][t] = (unsigned char)__float2int_rn(idx);
        }
    }

    // ---- prologue: full A column s -> 64 packed f32x2 (128 regs) ----
    unsigned long long Ar[64];
    if (isCompute) {
        #pragma unroll
        for (int j = 0; j < 64; j++) {
            float a0 = Amat[(2 * j) * NS + s];
            float a1 = Amat[(2 * j + 1) * NS + s];
            Ar[j] = pk(a0, a1);
        }
    }
    __syncthreads();

    // ---- init: v0 = E0*I per group; prime relay ----
    if (isCompute) {
        int o0 = obs_sm[g][0];
        ubuf[g][0][s] = Bsh[o0 * NS + s] * Ivec[s];
    } else {
        if (lane < 8) {
            zs1[0][0][lane] = 0.125f; zs1[0][1][lane] = 0.125f;   // Z=1 -> e=0
            zs1[1][0][lane] = 0.125f; zs1[1][1][lane] = 0.125f;
        }
        if (lane == 0) {
            sc_sm[0][0] = 1.0f; sc_sm[0][1] = 1.0f;
            sc_sm[1][0] = 1.0f; sc_sm[1][1] = 1.0f;
        }
    }
    __syncthreads();

    int   Stot0 = 0, Stot1 = 0;           // (valid on tid==256)
    float Elast = 0.f, Rlast = 0.f, vlast = 0.f;

    // ---- main recurrence: ONE barrier per step, two batches interleaved ----
    for (int t = 1; t < TLEN; t++) {
        const int pb = (t - 1) & 1, cb = t & 1;

        if (isCompute) {
            // prefetch emission * scale (independent of FMA chain)
            int o = obs_sm[g][t];
            float scf = sc_sm[g][pb];
            float E = Bsh[o * NS + s];
            float Escf = E * scf;

            // full dot: R[s] = sum_k v_{t-1}[k] * A[k][s]
            const ulonglong2* up = (const ulonglong2*)ubuf[g][pb];   // 32 x 16B broadcast
            unsigned long long acc[8];
            #pragma unroll
            for (int j = 0; j < 4; j++) {
                ulonglong2 c = up[j];
                acc[2 * j]     = mul2(c.x, Ar[2 * j]);
                acc[2 * j + 1] = mul2(c.y, Ar[2 * j + 1]);
            }
            #pragma unroll
            for (int j = 4; j < 32; j++) {
                ulonglong2 c = up[j];
                fma2(acc[(2 * j) & 7],     c.x, Ar[2 * j]);
                fma2(acc[(2 * j + 1) & 7], c.y, Ar[2 * j + 1]);
            }
            unsigned long long p0 = padd(padd(acc[0], acc[1]), padd(acc[2], acc[3]));
            unsigned long long p1 = padd(padd(acc[4], acc[5]), padd(acc[6], acc[7]));
            float R = hsum2(padd(p0, p1));

            float v = Escf * R;
            ubuf[g][cb][s] = v;
            Elast = E; Rlast = R; vlast = v;
        } else {
            // ---- relay warp: stale-Z pow2 controllers for BOTH groups ----
            #pragma unroll
            for (int gg = 0; gg < 2; gg++) {
                float4 za, zb;
                if (lane == 0) {
                    za = *(const float4*)&zs1[gg][pb][0];
                    zb = *(const float4*)&zs1[gg][pb][4];
                }
                float4 a = ((const float4*)ubuf[gg][pb])[lane];
                float zsum = (a.x + a.y) + (a.z + a.w);
                zsum += __shfl_xor_sync(0xffffffffu, zsum, 1);
                zsum += __shfl_xor_sync(0xffffffffu, zsum, 2);
                if ((lane & 3) == 0) zs1[gg][cb][lane >> 2] = zsum;
                if (lane == 0) {
                    float Z = ((za.x + za.y) + (za.z + za.w)) + ((zb.x + zb.y) + (zb.z + zb.w));
                    int e = ((((__float_as_int(Z) >> 23) & 255) - 127) >> 2);  // damped
                    if (t < TLEN - 1) { if (gg == 0) Stot0 += e; else Stot1 += e; }
                    sc_sm[gg][cb] = __int_as_float((127 - e) << 23);   // 2^{-e}, exact
                }
            }
        }
        __syncthreads();   // v_t, zs1, scf all published
    }

    // ---- epilogue ----
    if (tid == 256) { stot_sm[0] = Stot0; stot_sm[1] = Stot1; }
    if (isCompute) {
        float rr = Rlast, vv = vlast;
        #pragma unroll
        for (int off = 16; off > 0; off >>= 1) {
            rr += __shfl_xor_sync(0xffffffffu, rr, off);
            vv += __shfl_xor_sync(0xffffffffu, vv, off);
        }
        if (lane == 0) { znext[g][wg] = rr; zvs[g][wg] = vv; }
    }
    __syncthreads();

    if (isCompute) {
        const int bout = 2 * blockIdx.x + g;
        float4 zn = *(const float4*)znext[g];
        float SR = (zn.x + zn.y) + (zn.z + zn.w);      // = sum(v_{T-2}) (A rows sum to 1)
        out[bout * NS + s] = Elast * Rlast / SR;       // alpha_f (pow2 factors cancel)
        if (s == 0) {
            float4 zv = *(const float4*)zvs[g];
            float SV = (zv.x + zv.y) + (zv.z + zv.w);  // sum(v_{T-1})
            double ll = log((double)SV) + (double)stot_sm[g] * 0.6931471805599453;
            out[BATCH * NS + bout] = (float)ll;        // loglik
        }
    }
}

extern "C" void kernel_launch(void* const* d_in, const int* in_sizes, int n_in,
                              void* d_out, int out_size)
{
    const float* inputs = (const float*)d_in[0];   // [128, 8192, 64]
    const float* Ivec   = (const float*)d_in[1];   // [128]
    const float* Amat   = (const float*)d_in[2];   // [128, 128]
    const float* Bmat   = (const float*)d_in[3];   // [64, 128]
    float* out = (float*)d_out;                    // alpha_f [128,128] ++ loglik [128]

    hmm_forward_kernel<<<BATCH / 2, NT>>>(inputs, Ivec, Amat, Bmat, out);
}

// round 10
// speedup vs baseline: 1.8016x; 1.8016x over previous
#include <cuda_runtime.h>
#include <cstdint>

#define TLEN   8192
#define BATCH  128
#define NS     128
#define EMITN  64
#define NT     160   // 4 compute warps (thread=state) + 1 relay warp

// ---- packed f32x2 helpers (sm_103a) ----
__device__ __forceinline__ void fma2(unsigned long long& d, unsigned long long a, unsigned long long b) {
    asm("fma.rn.f32x2 %0, %1, %2, %0;" : "+l"(d) : "l"(a), "l"(b));
}
__device__ __forceinline__ unsigned long long mul2(unsigned long long a, unsigned long long b) {
    unsigned long long d;
    asm("mul.rn.f32x2 %0, %1, %2;" : "=l"(d) : "l"(a), "l"(b));
    return d;
}
__device__ __forceinline__ unsigned long long padd(unsigned long long a, unsigned long long b) {
    unsigned long long d;
    asm("add.rn.f32x2 %0, %1, %2;" : "=l"(d) : "l"(a), "l"(b));
    return d;
}
__device__ __forceinline__ unsigned long long pk(float lo, float hi) {
    unsigned long long r;
    asm("mov.b64 %0, {%1, %2};" : "=l"(r) : "f"(lo), "f"(hi));
    return r;
}
__device__ __forceinline__ float hsum2(unsigned long long v) {
    float lo, hi;
    asm("mov.b64 {%0, %1}, %2;" : "=f"(lo), "=f"(hi) : "l"(v));
    return lo + hi;
}

__global__ __launch_bounds__(NT, 1)
void hmm_forward_kernel(const float* __restrict__ inputs,
                        const float* __restrict__ Ivec,
                        const float* __restrict__ Amat,
                        const float* __restrict__ Bmat,
                        float* __restrict__ out)
{
    __shared__ float Bsh[EMITN * NS];              // 32 KB
    __shared__ unsigned char obs_sm[TLEN];         // 8 KB
    __shared__ __align__(16) float ubuf[2][NS];    // double-buffered v_t
    __shared__ __align__(16) float zs1[2][8];      // relay stage-1 partials
    __shared__ float sc_sm[2];                     // exact pow2 scale (relay output)
    __shared__ __align__(16) float znext[4];
    __shared__ __align__(16) float zvs[4];
    __shared__ int stot_sm;

    const int tid  = threadIdx.x;
    const int s    = tid & 127;     // state index (compute threads)
    const int w    = tid >> 5;
    const int lane = tid & 31;
    const int b    = blockIdx.x;
    const bool isCompute = (tid < 128);

    // ---- prologue: B into smem ----
    for (int i = tid; i < EMITN * NS; i += NT) Bsh[i] = Bmat[i];

    // ---- prologue: one-hot -> obs index (exact dot with iota) ----
    {
        const float* xin = inputs + (size_t)b * TLEN * EMITN;
        for (int t = tid; t < TLEN; t += NT) {
            const float4* r = (const float4*)(xin + (size_t)t * EMITN);
            float idx = 0.0f;
            #pragma unroll
            for (int j = 0; j < 16; j++) {
                float4 v = r[j];
                idx = fmaf((float)(4 * j + 0), v.x, idx);
                idx = fmaf((float)(4 * j + 1), v.y, idx);
                idx = fmaf((float)(4 * j + 2), v.z, idx);
                idx = fmaf((float)(4 * j + 3), v.w, idx);
            }
            obs_sm[t] = (unsigned char)__float2int_rn(idx);
        }
    }

    // ---- prologue: full A column s into registers (64 packed f32x2) ----
    unsigned long long Ar[64];
    if (isCompute) {
        #pragma unroll
        for (int j = 0; j < 64; j++) {
            float a0 = Amat[(2 * j) * NS + s];
            float a1 = Amat[(2 * j + 1) * NS + s];
            Ar[j] = pk(a0, a1);
        }
    }

    // ---- init: v0 = E0*I, relay buffers ----
    if (isCompute) {
        float Ival = Ivec[s];
        __syncthreads();           // Bsh + obs ready
        int o0 = obs_sm[0];
        ubuf[0][s] = Bsh[o0 * NS + s] * Ival;
    } else {
        __syncthreads();
        if (lane < 8) { zs1[0][lane] = 0.125f; zs1[1][lane] = 0.125f; }  // Z=1 -> e=0
        if (lane == 0) { sc_sm[0] = 1.0f; sc_sm[1] = 1.0f; }
    }
    __syncthreads();

    int   Stot  = 0;                  // (valid on tid==128)
    float Elast = 0.f, Rlast = 0.f, vlast = 0.f;

    // ---- main recurrence: ONE barrier per step, 3-group load skew ----
    for (int t = 1; t < TLEN; t++) {
        const int pb = (t - 1) & 1, cb = t & 1;

        if (isCompute) {
            // scalar prefetches first: results needed only at the step tail
            float scf = sc_sm[pb];
            int o = obs_sm[t];
            float E = Bsh[o * NS + s];

            const ulonglong2* up = (const ulonglong2*)ubuf[pb];   // 32 x 16B, broadcast
            ulonglong2 c[32];
            unsigned long long acc[8];

            // preload groups 0..2 (12 LDS.128) -> MLP 12 up front
            #pragma unroll
            for (int j = 0; j < 12; j++) c[j] = up[j];

            // group 0 FMAs (init accumulators)
            #pragma unroll
            for (int j = 0; j < 4; j++) {
                acc[2 * j]     = mul2(c[j].x, Ar[2 * j]);
                acc[2 * j + 1] = mul2(c[j].y, Ar[2 * j + 1]);
            }

            // groups 1..7: FMA group g while loading group g+2
            #pragma unroll
            for (int g = 1; g < 8; g++) {
                if (g + 2 < 8) {
                    #pragma unroll
                    for (int j = 4 * (g + 2); j < 4 * (g + 2) + 4; j++) c[j] = up[j];
                }
                #pragma unroll
                for (int j = 4 * g; j < 4 * g + 4; j++) {
                    fma2(acc[(2 * j) & 7],     c[j].x, Ar[2 * j]);
                    fma2(acc[(2 * j + 1) & 7], c[j].y, Ar[2 * j + 1]);
                }
            }

            unsigned long long p0 = padd(padd(acc[0], acc[1]), padd(acc[2], acc[3]));
            unsigned long long p1 = padd(padd(acc[4], acc[5]), padd(acc[6], acc[7]));
            float R = hsum2(padd(p0, p1));

            float v = (E * scf) * R;
            ubuf[cb][s] = v;
            Elast = E; Rlast = R; vlast = v;
        } else {
            // ---- relay warp: pipelined stale-Z pow2 controller (delay-3, gain 1/4) ----
            float4 za, zb;
            if (lane == 0) {   // stage B inputs: last step's partials
                za = *(const float4*)&zs1[pb][0];
                zb = *(const float4*)&zs1[pb][4];
            }
            float4 a = ((const float4*)ubuf[pb])[lane];
            float zsum = (a.x + a.y) + (a.z + a.w);
            zsum += __shfl_xor_sync(0xffffffffu, zsum, 1);
            zsum += __shfl_xor_sync(0xffffffffu, zsum, 2);
            if ((lane & 3) == 0) zs1[cb][lane >> 2] = zsum;
            if (lane == 0) {
                float Z = ((za.x + za.y) + (za.z + za.w)) + ((zb.x + zb.y) + (zb.z + zb.w));
                int e = ((((__float_as_int(Z) >> 23) & 255) - 127) >> 2);  // damped
                if (t < TLEN - 1) Stot += e;
                sc_sm[cb] = __int_as_float((127 - e) << 23);   // 2^{-e}, exact
            }
        }
        __syncthreads();   // v_t, zs1, scf all published
    }

    // ---- epilogue ----
    if (isCompute) {
        float rr = Rlast, vv = vlast;
        #pragma unroll
        for (int off = 16; off > 0; off >>= 1) {
            rr += __shfl_xor_sync(0xffffffffu, rr, off);
            vv += __shfl_xor_sync(0xffffffffu, vv, off);
        }
        if (lane == 0) { znext[w] = rr; zvs[w] = vv; }
    } else if (tid == 128) {
        stot_sm = Stot;
    }
    __syncthreads();

    if (isCompute) {
        float4 zn = *(const float4*)znext;
        float SR = (zn.x + zn.y) + (zn.z + zn.w);      // = sum(v_{T-2}) (A rows sum to 1)
        out[b * NS + s] = Elast * Rlast / SR;          // alpha_f (pow2 factors cancel)
    }
    if (tid == 0) {
        float4 zv = *(const float4*)zvs;
        float SV = (zv.x + zv.y) + (zv.z + zv.w);      // sum(v_{T-1})
        double ll = log((double)SV) + (double)stot_sm * 0.6931471805599453;
        out[BATCH * NS + b] = (float)ll;               // loglik
    }
}

extern "C" void kernel_launch(void* const* d_in, const int* in_sizes, int n_in,
                              void* d_out, int out_size)
{
    const float* inputs = (const float*)d_in[0];   // [128, 8192, 64]
    const float* Ivec   = (const float*)d_in[1];   // [128]
    const float* Amat   = (const float*)d_in[2];   // [128, 128]
    const float* Bmat   = (const float*)d_in[3];   // [64, 128]
    float* out = (float*)d_out;                    // alpha_f [128,128] ++ loglik [128]

    hmm_forward_kernel<<<BATCH, NT>>>(inputs, Ivec, Amat, Bmat, out);
}

// round 12
// speedup vs baseline: 2.1496x; 1.1932x over previous
#include <cuda_runtime.h>
#include <cstdint>

#define TLEN   8192
#define BATCH  128
#define NS     128
#define EMITN  64
#define NT     160      // 4 compute warps + 1 relay warp
#define HALF   4096     // chunk boundary (chunk1 covers emissions 0..4096)
#define WARM   64       // chunk2 warmup steps
#define OBSBUF 4224     // max obs window (chunk2: 4160 entries)

// ---- packed f32x2 helpers (sm_103a) ----
__device__ __forceinline__ void fma2(unsigned long long& d, unsigned long long a, unsigned long long b) {
    asm("fma.rn.f32x2 %0, %1, %2, %0;" : "+l"(d) : "l"(a), "l"(b));
}
__device__ __forceinline__ unsigned long long mul2(unsigned long long a, unsigned long long b) {
    unsigned long long d;
    asm("mul.rn.f32x2 %0, %1, %2;" : "=l"(d) : "l"(a), "l"(b));
    return d;
}
__device__ __forceinline__ unsigned long long padd(unsigned long long a, unsigned long long b) {
    unsigned long long d;
    asm("add.rn.f32x2 %0, %1, %2;" : "=l"(d) : "l"(a), "l"(b));
    return d;
}
__device__ __forceinline__ unsigned long long pk(float lo, float hi) {
    unsigned long long r;
    asm("mov.b64 %0, {%1, %2};" : "=l"(r) : "f"(lo), "f"(hi));
    return r;
}
__device__ __forceinline__ float hsum2(unsigned long long v) {
    float lo, hi;
    asm("mov.b64 {%0, %1}, %2;" : "=f"(lo), "=f"(hi) : "l"(v));
    return lo + hi;
}

__device__ double g_L1[BATCH];
__device__ double g_L2[BATCH];

// one recurrence segment: steps t0..t1 inclusive, one barrier per step
__device__ __forceinline__ void run_steps(
    int t0, int t1, int tbase, bool isCompute, int s, int lane,
    const unsigned long long (&Ar)[64],
    const float* __restrict__ Bsh, const unsigned char* __restrict__ obs_sm,
    float (*ubuf)[NS], float (*zs1)[8], float* sc_sm,
    float& Elast, float& Rlast, float& vlast, int& Stot, int& eLast)
{
    for (int t = t0; t <= t1; t++) {
        const int pb = (t - 1) & 1, cb = t & 1;
        if (isCompute) {
            float scf = sc_sm[pb];
            int o = obs_sm[t - tbase];
            float E = Bsh[o * NS + s];

            const ulonglong2* up = (const ulonglong2*)ubuf[pb];
            unsigned long long acc[8];
            #pragma unroll
            for (int j = 0; j < 4; j++) {
                ulonglong2 c = up[j];
                acc[2 * j]     = mul2(c.x, Ar[2 * j]);
                acc[2 * j + 1] = mul2(c.y, Ar[2 * j + 1]);
            }
            #pragma unroll
            for (int j = 4; j < 32; j++) {
                ulonglong2 c = up[j];
                fma2(acc[(2 * j) & 7],     c.x, Ar[2 * j]);
                fma2(acc[(2 * j + 1) & 7], c.y, Ar[2 * j + 1]);
            }
            unsigned long long p0 = padd(padd(acc[0], acc[1]), padd(acc[2], acc[3]));
            unsigned long long p1 = padd(padd(acc[4], acc[5]), padd(acc[6], acc[7]));
            float R = hsum2(padd(p0, p1));

            float v = (E * scf) * R;
            ubuf[cb][s] = v;
            Elast = E; Rlast = R; vlast = v;
        } else {
            // relay warp: stale-Z (delay-3) damped exact-pow2 controller
            float4 za, zb;
            if (lane == 0) {
                za = *(const float4*)&zs1[pb][0];
                zb = *(const float4*)&zs1[pb][4];
            }
            float4 a = ((const float4*)ubuf[pb])[lane];
            float zsum = (a.x + a.y) + (a.z + a.w);
            zsum += __shfl_xor_sync(0xffffffffu, zsum, 1);
            zsum += __shfl_xor_sync(0xffffffffu, zsum, 2);
            if ((lane & 3) == 0) zs1[cb][lane >> 2] = zsum;
            if (lane == 0) {
                float Z = ((za.x + za.y) + (za.z + za.w)) + ((zb.x + zb.y) + (zb.z + zb.w));
                int e = ((((__float_as_int(Z) >> 23) & 255) - 127) >> 2);  // damped gain 1/4
                Stot += e; eLast = e;               // e_t applied at step t+1
                sc_sm[cb] = __int_as_float((127 - e) << 23);   // 2^{-e}, exact
            }
        }
        __syncthreads();
    }
}

__global__ __launch_bounds__(NT, 2)
void hmm_chunk_kernel(const float* __restrict__ inputs,
                      const float* __restrict__ Ivec,
                      const float* __restrict__ Amat,
                      const float* __restrict__ Bmat,
                      float* __restrict__ out)
{
    __shared__ float Bsh[EMITN * NS];              // 32 KB
    __shared__ unsigned char obs_sm[OBSBUF];       // 4.2 KB (chunk window only)
    __shared__ __align__(16) float ubuf[2][NS];
    __shared__ __align__(16) float zs1[2][8];
    __shared__ float sc_sm[2];
    __shared__ __align__(16) float znext[4];
    __shared__ __align__(16) float zvs[4];
    __shared__ int stot_sm;
    __shared__ double snapL;

    const int tid  = threadIdx.x;
    const int s    = tid & 127;
    const int w    = tid >> 5;
    const int lane = tid & 31;
    const bool isCompute = (tid < 128);

    const int b   = blockIdx.x >> 1;     // batch
    const int cid = blockIdx.x & 1;      // 0 = first half, 1 = second half
    const int tbase  = cid ? (HALF - WARM) : 0;                 // first stored obs index
    const int tcount = cid ? (TLEN - (HALF - WARM)) : (HALF + 1);

    // ---- prologue: B into smem ----
    for (int i = tid; i < EMITN * NS; i += NT) Bsh[i] = Bmat[i];

    // ---- prologue: one-hot -> obs index, own window only ----
    {
        const float* xin = inputs + (size_t)b * TLEN * EMITN;
        for (int tt = tid; tt < tcount; tt += NT) {
            const float4* r = (const float4*)(xin + (size_t)(tbase + tt) * EMITN);
            float idx = 0.0f;
            #pragma unroll
            for (int j = 0; j < 16; j++) {
                float4 v = r[j];
                idx = fmaf((float)(4 * j + 0), v.x, idx);
                idx = fmaf((float)(4 * j + 1), v.y, idx);
                idx = fmaf((float)(4 * j + 2), v.z, idx);
                idx = fmaf((float)(4 * j + 3), v.w, idx);
            }
            obs_sm[tt] = (unsigned char)__float2int_rn(idx);
        }
    }

    // ---- prologue: full A column s into registers ----
    unsigned long long Ar[64];
    if (isCompute) {
        #pragma unroll
        for (int j = 0; j < 64; j++) {
            float a0 = Amat[(2 * j) * NS + s];
            float a1 = Amat[(2 * j + 1) * NS + s];
            Ar[j] = pk(a0, a1);
        }
    }
    float Ival = isCompute ? Ivec[s] : 0.0f;
    __syncthreads();

    // ---- init vector (parity of tbase is even in both chunks -> ubuf[0]) ----
    if (isCompute) {
        if (cid == 0) {
            int o0 = obs_sm[0];                      // t = 0
            ubuf[0][s] = Bsh[o0 * NS + s] * Ival;    // F_0 = E_0 * I
        } else {
            ubuf[0][s] = 0.0078125f;                 // uniform warmup start
        }
    } else {
        if (lane < 8) { zs1[0][lane] = 0.125f; zs1[1][lane] = 0.125f; }  // Z=1 -> e=0
        if (lane == 0) { sc_sm[0] = 1.0f; sc_sm[1] = 1.0f; }
    }
    __syncthreads();

    int   Stot = 0, eLast = 0;                       // valid on tid==128 (relay lane 0)
    float Elast = 0.f, Rlast = 0.f, vlast = 0.f;

    if (cid == 0) {
        // ======== chunk 1: exact forward, t = 1..HALF ========
        run_steps(1, HALF, tbase, isCompute, s, lane, Ar, Bsh, obs_sm,
                  ubuf, zs1, sc_sm, Elast, Rlast, vlast, Stot, eLast);

        // epilogue: L1 = log sum F_HALF  (v_HALF scaled by 2^{Stot-eLast})
        if (tid == 128) stot_sm = Stot - eLast;      // eLast applied only at HALF+1
        if (isCompute) {
            float vv = vlast;
            #pragma unroll
            for (int off = 16; off > 0; off >>= 1) vv += __shfl_xor_sync(0xffffffffu, vv, off);
            if (lane == 0) zvs[w] = vv;
        }
        __syncthreads();
        if (tid == 0) {
            float4 zv = *(const float4*)zvs;
            float SV = (zv.x + zv.y) + (zv.z + zv.w);
            g_L1[b] = log((double)SV) + (double)stot_sm * 0.6931471805599453;
        }
    } else {
        // ======== chunk 2: warmup t = HALF-WARM+1 .. HALF ========
        run_steps(HALF - WARM + 1, HALF, tbase, isCompute, s, lane, Ar, Bsh, obs_sm,
                  ubuf, zs1, sc_sm, Elast, Rlast, vlast, Stot, eLast);

        // snapshot: log sum v_HALF + S(v_HALF) ln2
        if (tid == 128) stot_sm = Stot - eLast;
        if (isCompute) {
            float vv = vlast;
            #pragma unroll
            for (int off = 16; off > 0; off >>= 1) vv += __shfl_xor_sync(0xffffffffu, vv, off);
            if (lane == 0) zvs[w] = vv;
        }
        __syncthreads();
        if (tid == 0) {
            float4 zv = *(const float4*)zvs;
            float SV = (zv.x + zv.y) + (zv.z + zv.w);
            snapL = log((double)SV) + (double)stot_sm * 0.6931471805599453;
        }
        __syncthreads();

        // ======== chunk 2 main: t = HALF+1 .. TLEN-1 ========
        run_steps(HALF + 1, TLEN - 1, tbase, isCompute, s, lane, Ar, Bsh, obs_sm,
                  ubuf, zs1, sc_sm, Elast, Rlast, vlast, Stot, eLast);

        // epilogue: alpha_f + L2
        if (tid == 128) stot_sm = Stot - eLast;
        if (isCompute) {
            float rr = Rlast, vv = vlast;
            #pragma unroll
            for (int off = 16; off > 0; off >>= 1) {
                rr += __shfl_xor_sync(0xffffffffu, rr, off);
                vv += __shfl_xor_sync(0xffffffffu, vv, off);
            }
            if (lane == 0) { znext[w] = rr; zvs[w] = vv; }
        }
        __syncthreads();

        if (isCompute) {
            float4 zn = *(const float4*)znext;
            float SR = (zn.x + zn.y) + (zn.z + zn.w);  // = sum v_{T-2} (A rows sum to 1)
            out[b * NS + s] = Elast * Rlast / SR;      // alpha_f (pow2 factors cancel)
        }
        if (tid == 0) {
            float4 zv = *(const float4*)zvs;
            float SV = (zv.x + zv.y) + (zv.z + zv.w);  // sum v_{T-1}
            double Lfin = log((double)SV) + (double)stot_sm * 0.6931471805599453;
            g_L2[b] = Lfin - snapL;
        }
    }
}

__global__ void ll_combine_kernel(float* __restrict__ out)
{
    int b = threadIdx.x;
    out[BATCH * NS + b] = (float)(g_L1[b] + g_L2[b]);
}

extern "C" void kernel_launch(void* const* d_in, const int* in_sizes, int n_in,
                              void* d_out, int out_size)
{
    const float* inputs = (const float*)d_in[0];   // [128, 8192, 64]
    const float* Ivec   = (const float*)d_in[1];   // [128]
    const float* Amat   = (const float*)d_in[2];   // [128, 128]
    const float* Bmat   = (const float*)d_in[3];   // [64, 128]
    float* out = (float*)d_out;                    // alpha_f [128,128] ++ loglik [128]

    hmm_chunk_kernel<<<2 * BATCH, NT>>>(inputs, Ivec, Amat, Bmat, out);
    ll_combine_kernel<<<1, BATCH>>>(out);
}

// round 13
// speedup vs baseline: 2.3557x; 1.0959x over previous
#include <cuda_runtime.h>
#include <cstdint>

#define TLEN   8192
#define BATCH  128
#define NS     128
#define EMITN  64
#define NT     160      // 4 compute warps + 1 relay warp
#define HALF   4096     // chunk boundary (chunk1 covers emissions 0..4096)
#define WARM   64       // chunk2 warmup steps
#define OBSBUF 4224     // max obs window (chunk2: 4160 entries)

// ---- packed f32x2 helpers (sm_103a) ----
__device__ __forceinline__ void fma2(unsigned long long& d, unsigned long long a, unsigned long long b) {
    asm("fma.rn.f32x2 %0, %1, %2, %0;" : "+l"(d) : "l"(a), "l"(b));
}
__device__ __forceinline__ unsigned long long mul2(unsigned long long a, unsigned long long b) {
    unsigned long long d;
    asm("mul.rn.f32x2 %0, %1, %2;" : "=l"(d) : "l"(a), "l"(b));
    return d;
}
__device__ __forceinline__ unsigned long long padd(unsigned long long a, unsigned long long b) {
    unsigned long long d;
    asm("add.rn.f32x2 %0, %1, %2;" : "=l"(d) : "l"(a), "l"(b));
    return d;
}
__device__ __forceinline__ unsigned long long pk(float lo, float hi) {
    unsigned long long r;
    asm("mov.b64 %0, {%1, %2};" : "=l"(r) : "f"(lo), "f"(hi));
    return r;
}
__device__ __forceinline__ float hsum2(unsigned long long v) {
    float lo, hi;
    asm("mov.b64 {%0, %1}, %2;" : "=f"(lo), "=f"(hi) : "l"(v));
    return lo + hi;
}

__device__ double g_L1[BATCH];
__device__ double g_L2[BATCH];

// one recurrence segment: steps t0..t1 inclusive, two-phase, warp-blocked K x S
__device__ __forceinline__ void run_steps(
    int t0, int t1, int tbase, bool isCompute, int w, int lane, int s,
    const unsigned long long (&Ar)[64],
    const float* __restrict__ Bsh, const unsigned char* __restrict__ obs_sm,
    float (*ubuf)[NS], float (*part)[NS], float (*zs1)[8], float* sc_sm,
    float& Elast, float& Rlast, float& vlast, int& Stot, int& eLast)
{
    for (int t = t0; t <= t1; t++) {
        const int pb = (t - 1) & 1, cb = t & 1;
        float E = 0.f, scf = 0.f;

        if (isCompute) {
            // scalar prefetches (consumed in phase 2)
            scf = sc_sm[pb];
            int o = obs_sm[t - tbase];
            E = Bsh[o * NS + s];

            // phase 1: own K-quarter only (8 broadcast LDS.128), all 128 states
            const ulonglong2* up = (const ulonglong2*)ubuf[pb] + 8 * w;
            ulonglong2 c[8];
            #pragma unroll
            for (int i = 0; i < 8; i++) c[i] = up[i];

            unsigned long long acc[8];        // acc[2j],acc[2j+1] for state 4*lane+j
            #pragma unroll
            for (int j = 0; j < 4; j++) {
                acc[2 * j]     = mul2(c[0].x, Ar[16 * j]);
                acc[2 * j + 1] = mul2(c[0].y, Ar[16 * j + 1]);
            }
            #pragma unroll
            for (int i = 1; i < 8; i++) {
                #pragma unroll
                for (int j = 0; j < 4; j++) {
                    fma2(acc[2 * j],     c[i].x, Ar[16 * j + 2 * i]);
                    fma2(acc[2 * j + 1], c[i].y, Ar[16 * j + 2 * i + 1]);
                }
            }
            float4 pf;
            pf.x = hsum2(padd(acc[0], acc[1]));
            pf.y = hsum2(padd(acc[2], acc[3]));
            pf.z = hsum2(padd(acc[4], acc[5]));
            pf.w = hsum2(padd(acc[6], acc[7]));
            *(float4*)&part[w][4 * lane] = pf;          // STS.128, contiguous
        } else {
            // relay warp: stale-Z (delay-3) damped exact-pow2 controller
            float4 za, zb;
            if (lane == 0) {
                za = *(const float4*)&zs1[pb][0];
                zb = *(const float4*)&zs1[pb][4];
            }
            float4 a = ((const float4*)ubuf[pb])[lane];
            float zsum = (a.x + a.y) + (a.z + a.w);
            zsum += __shfl_xor_sync(0xffffffffu, zsum, 1);
            zsum += __shfl_xor_sync(0xffffffffu, zsum, 2);
            if ((lane & 3) == 0) zs1[cb][lane >> 2] = zsum;
            if (lane == 0) {
                float Z = ((za.x + za.y) + (za.z + za.w)) + ((zb.x + zb.y) + (zb.z + zb.w));
                int e = ((((__float_as_int(Z) >> 23) & 255) - 127) >> 2);  // damped gain 1/4
                Stot += e; eLast = e;               // e_t applied at step t+1
                sc_sm[cb] = __int_as_float((127 - e) << 23);   // 2^{-e}, exact
            }
        }
        __syncthreads();                        // BAR1: partials + relay outputs

        if (isCompute) {
            // phase 2: tiny combine (4 strided LDS.32, 1 wf each)
            float R = (part[0][s] + part[1][s]) + (part[2][s] + part[3][s]);
            float v = (E * scf) * R;
            ubuf[cb][s] = v;
            Elast = E; Rlast = R; vlast = v;
        }
        __syncthreads();                        // BAR2: v_t published
    }
}

__global__ __launch_bounds__(NT, 2)
void hmm_chunk_kernel(const float* __restrict__ inputs,
                      const float* __restrict__ Ivec,
                      const float* __restrict__ Amat,
                      const float* __restrict__ Bmat,
                      float* __restrict__ out)
{
    __shared__ float Bsh[EMITN * NS];              // 32 KB
    __shared__ unsigned char obs_sm[OBSBUF];       // 4.2 KB (chunk window only)
    __shared__ __align__(16) float ubuf[2][NS];
    __shared__ __align__(16) float part[4][NS];    // per-quarter partials
    __shared__ __align__(16) float zs1[2][8];
    __shared__ float sc_sm[2];
    __shared__ __align__(16) float znext[4];
    __shared__ __align__(16) float zvs[4];
    __shared__ int stot_sm;
    __shared__ double snapL;

    const int tid  = threadIdx.x;
    const int s    = tid & 127;
    const int w    = tid >> 5;          // compute: K-quarter id (0..3)
    const int lane = tid & 31;
    const bool isCompute = (tid < 128);

    const int b   = blockIdx.x >> 1;     // batch
    const int cid = blockIdx.x & 1;      // 0 = first half, 1 = second half
    const int tbase  = cid ? (HALF - WARM) : 0;
    const int tcount = cid ? (TLEN - (HALF - WARM)) : (HALF + 1);

    // ---- prologue: B into smem ----
    for (int i = tid; i < EMITN * NS; i += NT) Bsh[i] = Bmat[i];

    // ---- prologue: one-hot -> obs index, own window only ----
    {
        const float* xin = inputs + (size_t)b * TLEN * EMITN;
        for (int tt = tid; tt < tcount; tt += NT) {
            const float4* r = (const float4*)(xin + (size_t)(tbase + tt) * EMITN);
            float idx = 0.0f;
            #pragma unroll
            for (int j = 0; j < 16; j++) {
                float4 v = r[j];
                idx = fmaf((float)(4 * j + 0), v.x, idx);
                idx = fmaf((float)(4 * j + 1), v.y, idx);
                idx = fmaf((float)(4 * j + 2), v.z, idx);
                idx = fmaf((float)(4 * j + 3), v.w, idx);
            }
            obs_sm[tt] = (unsigned char)__float2int_rn(idx);
        }
    }

    // ---- prologue: A block [32w..32w+32) x {4*lane..4*lane+3} -> 64 packed u64 ----
    unsigned long long Ar[64];
    if (isCompute) {
        #pragma unroll
        for (int j = 0; j < 4; j++) {
            const int sj = 4 * lane + j;
            #pragma unroll
            for (int i = 0; i < 8; i++) {
                const int k0 = 32 * w + 4 * i;
                Ar[16 * j + 2 * i]     = pk(Amat[(k0 + 0) * NS + sj], Amat[(k0 + 1) * NS + sj]);
                Ar[16 * j + 2 * i + 1] = pk(Amat[(k0 + 2) * NS + sj], Amat[(k0 + 3) * NS + sj]);
            }
        }
    }
    float Ival = isCompute ? Ivec[s] : 0.0f;
    __syncthreads();

    // ---- init vector ----
    if (isCompute) {
        if (cid == 0) {
            int o0 = obs_sm[0];
            ubuf[0][s] = Bsh[o0 * NS + s] * Ival;    // F_0 = E_0 * I
        } else {
            ubuf[0][s] = 0.0078125f;                 // uniform warmup start
        }
    } else {
        if (lane < 8) { zs1[0][lane] = 0.125f; zs1[1][lane] = 0.125f; }  // Z=1 -> e=0
        if (lane == 0) { sc_sm[0] = 1.0f; sc_sm[1] = 1.0f; }
    }
    __syncthreads();

    int   Stot = 0, eLast = 0;                       // valid on tid==128 (relay lane 0)
    float Elast = 0.f, Rlast = 0.f, vlast = 0.f;

    if (cid == 0) {
        // ======== chunk 1: exact forward, t = 1..HALF ========
        run_steps(1, HALF, tbase, isCompute, w, lane, s, Ar, Bsh, obs_sm,
                  ubuf, part, zs1, sc_sm, Elast, Rlast, vlast, Stot, eLast);

        if (tid == 128) stot_sm = Stot - eLast;
        if (isCompute) {
            float vv = vlast;
            #pragma unroll
            for (int off = 16; off > 0; off >>= 1) vv += __shfl_xor_sync(0xffffffffu, vv, off);
            if (lane == 0) zvs[w] = vv;
        }
        __syncthreads();
        if (tid == 0) {
            float4 zv = *(const float4*)zvs;
            float SV = (zv.x + zv.y) + (zv.z + zv.w);
            g_L1[b] = log((double)SV) + (double)stot_sm * 0.6931471805599453;
        }
    } else {
        // ======== chunk 2: warmup t = HALF-WARM+1 .. HALF ========
        run_steps(HALF - WARM + 1, HALF, tbase, isCompute, w, lane, s, Ar, Bsh, obs_sm,
                  ubuf, part, zs1, sc_sm, Elast, Rlast, vlast, Stot, eLast);

        if (tid == 128) stot_sm = Stot - eLast;
        if (isCompute) {
            float vv = vlast;
            #pragma unroll
            for (int off = 16; off > 0; off >>= 1) vv += __shfl_xor_sync(0xffffffffu, vv, off);
            if (lane == 0) zvs[w] = vv;
        }
        __syncthreads();
        if (tid == 0) {
            float4 zv = *(const float4*)zvs;
            float SV = (zv.x + zv.y) + (zv.z + zv.w);
            snapL = log((double)SV) + (double)stot_sm * 0.6931471805599453;
        }
        __syncthreads();

        // ======== chunk 2 main: t = HALF+1 .. TLEN-1 ========
        run_steps(HALF + 1, TLEN - 1, tbase, isCompute, w, lane, s, Ar, Bsh, obs_sm,
                  ubuf, part, zs1, sc_sm, Elast, Rlast, vlast, Stot, eLast);

        if (tid == 128) stot_sm = Stot - eLast;
        if (isCompute) {
            float rr = Rlast, vv = vlast;
            #pragma unroll
            for (int off = 16; off > 0; off >>= 1) {
                rr += __shfl_xor_sync(0xffffffffu, rr, off);
                vv += __shfl_xor_sync(0xffffffffu, vv, off);
            }
            if (lane == 0) { znext[w] = rr; zvs[w] = vv; }
        }
        __syncthreads();

        if (isCompute) {
            float4 zn = *(const float4*)znext;
            float SR = (zn.x + zn.y) + (zn.z + zn.w);  // = sum v_{T-2} (A rows sum to 1)
            out[b * NS + s] = Elast * Rlast / SR;      // alpha_f (pow2 factors cancel)
        }
        if (tid == 0) {
            float4 zv = *(const float4*)zvs;
            float SV = (zv.x + zv.y) + (zv.z + zv.w);  // sum v_{T-1}
            double Lfin = log((double)SV) + (double)stot_sm * 0.6931471805599453;
            g_L2[b] = Lfin - snapL;
        }
    }
}

__global__ void ll_combine_kernel(float* __restrict__ out)
{
    int b = threadIdx.x;
    out[BATCH * NS + b] = (float)(g_L1[b] + g_L2[b]);
}

extern "C" void kernel_launch(void* const* d_in, const int* in_sizes, int n_in,
                              void* d_out, int out_size)
{
    const float* inputs = (const float*)d_in[0];   // [128, 8192, 64]
    const float* Ivec   = (const float*)d_in[1];   // [128]
    const float* Amat   = (const float*)d_in[2];   // [128, 128]
    const float* Bmat   = (const float*)d_in[3];   // [64, 128]
    float* out = (float*)d_out;                    // alpha_f [128,128] ++ loglik [128]

    hmm_chunk_kernel<<<2 * BATCH, NT>>>(inputs, Ivec, Amat, Bmat, out);
    ll_combine_kernel<<<1, BATCH>>>(out);
}

// round 14
// speedup vs baseline: 2.8152x; 1.1951x over previous
#include <cuda_runtime.h>
#include <cstdint>

#define TLEN   8192
#define BATCH  128
#define NS     128
#define EMITN  64
#define NT     160      // 4 compute warps + 1 relay warp
#define HALF   4128     // chunk boundary (balanced: 4128 vs 64+4063)
#define WARM   64       // chunk2 warmup steps
#define OBSBUF 4160

// ---- packed f32x2 helpers (sm_103a) ----
__device__ __forceinline__ void fma2(unsigned long long& d, unsigned long long a, unsigned long long b) {
    asm("fma.rn.f32x2 %0, %1, %2, %0;" : "+l"(d) : "l"(a), "l"(b));
}
__device__ __forceinline__ unsigned long long mul2(unsigned long long a, unsigned long long b) {
    unsigned long long d;
    asm("mul.rn.f32x2 %0, %1, %2;" : "=l"(d) : "l"(a), "l"(b));
    return d;
}
__device__ __forceinline__ unsigned long long padd(unsigned long long a, unsigned long long b) {
    unsigned long long d;
    asm("add.rn.f32x2 %0, %1, %2;" : "=l"(d) : "l"(a), "l"(b));
    return d;
}
__device__ __forceinline__ unsigned long long pk(float lo, float hi) {
    unsigned long long r;
    asm("mov.b64 %0, {%1, %2};" : "=l"(r) : "f"(lo), "f"(hi));
    return r;
}
__device__ __forceinline__ float hsum2(unsigned long long v) {
    float lo, hi;
    asm("mov.b64 {%0, %1}, %2;" : "=f"(lo), "=f"(hi) : "l"(v));
    return lo + hi;
}

__device__ double g_L1[BATCH];
__device__ double g_L2[BATCH];

// iterations t0..t1: ONE __syncthreads() per step.
// iteration t: (compute) fuse-combine v_{t-1} from part[pb] warp-locally,
// then produce part[cb] = partial dots for step t.  (relay) stale-Z controller.
__device__ __forceinline__ void run_steps(
    int t0, int t1, int tbase, bool isCompute, int w, int lane, int qs,
    const unsigned long long (&Ar)[64],
    const float* __restrict__ Bsh, const unsigned char* __restrict__ obs_sm,
    float (*ubuf)[NS], float (*part)[4][NS], float (*zs1)[8], float* sc_sm,
    int& Stot)
{
    for (int t = t0; t <= t1; t++) {
        const int pb = (t - 1) & 1, cb = t & 1;
        if (isCompute) {
            // fused combine: v_{t-1}[qs], qs = 32w + lane (own quarter only)
            float scf = sc_sm[pb];
            int o = obs_sm[t - 1 - tbase];
            float Eq = Bsh[o * NS + qs];
            float R4 = (part[pb][0][qs] + part[pb][1][qs])
                     + (part[pb][2][qs] + part[pb][3][qs]);
            float vq = (Eq * scf) * R4;
            ubuf[pb][qs] = vq;
            __syncwarp();

            // phase 1: own K-quarter (8 broadcast LDS.128), all 128 states
            const ulonglong2* up = (const ulonglong2*)ubuf[pb] + 8 * w;
            ulonglong2 c[8];
            #pragma unroll
            for (int i = 0; i < 8; i++) c[i] = up[i];

            unsigned long long acc[8];         // acc[2j],acc[2j+1] -> state 4*lane+j
            #pragma unroll
            for (int j = 0; j < 4; j++) {
                acc[2 * j]     = mul2(c[0].x, Ar[16 * j]);
                acc[2 * j + 1] = mul2(c[0].y, Ar[16 * j + 1]);
            }
            #pragma unroll
            for (int i = 1; i < 8; i++) {
                #pragma unroll
                for (int j = 0; j < 4; j++) {
                    fma2(acc[2 * j],     c[i].x, Ar[16 * j + 2 * i]);
                    fma2(acc[2 * j + 1], c[i].y, Ar[16 * j + 2 * i + 1]);
                }
            }
            float4 pf;
            pf.x = hsum2(padd(acc[0], acc[1]));
            pf.y = hsum2(padd(acc[2], acc[3]));
            pf.z = hsum2(padd(acc[4], acc[5]));
            pf.w = hsum2(padd(acc[6], acc[7]));
            *(float4*)&part[cb][w][4 * lane] = pf;      // STS.128
        } else {
            // relay: reads v_{t-2} (ubuf[cb]); 2-stage pipelined sum; damped pow2
            float4 za, zb;
            if (lane == 0) {
                za = *(const float4*)&zs1[pb][0];
                zb = *(const float4*)&zs1[pb][4];
            }
            float4 a = ((const float4*)ubuf[cb])[lane];
            float zsum = (a.x + a.y) + (a.z + a.w);
            zsum += __shfl_xor_sync(0xffffffffu, zsum, 1);
            zsum += __shfl_xor_sync(0xffffffffu, zsum, 2);
            if ((lane & 3) == 0) zs1[cb][lane >> 2] = zsum;
            if (lane == 0) {
                float Z = ((za.x + za.y) + (za.z + za.w)) + ((zb.x + zb.y) + (zb.z + zb.w));
                int e = ((((__float_as_int(Z) >> 23) & 255) - 127) >> 2);  // gain 1/4
                Stot += e;                                 // e_t applied at combine t+1
                sc_sm[cb] = __int_as_float((127 - e) << 23);   // 2^{-e}, exact
            }
        }
        __syncthreads();
    }
}

__global__ __launch_bounds__(NT, 2)
void hmm_chunk_kernel(const float* __restrict__ inputs,
                      const float* __restrict__ Ivec,
                      const float* __restrict__ Amat,
                      const float* __restrict__ Bmat,
                      float* __restrict__ out)
{
    __shared__ float Bsh[EMITN * NS];               // 32 KB
    __shared__ unsigned char obs_sm[OBSBUF];        // 4.1 KB
    __shared__ __align__(16) float ubuf[2][NS];
    __shared__ __align__(16) float part[2][4][NS];  // parity double-buffered partials
    __shared__ __align__(16) float zs1[2][8];
    __shared__ float sc_sm[2];
    __shared__ __align__(16) float znext[4];
    __shared__ __align__(16) float zvs[4];
    __shared__ int stot_sm;
    __shared__ double snapL;

    const int tid  = threadIdx.x;
    const int s    = tid & 127;
    const int w    = tid >> 5;          // compute: K-quarter id (0..3)
    const int lane = tid & 31;
    const int qs   = 32 * (w & 3) + lane;   // combine state for compute warps
    const bool isCompute = (tid < 128);

    const int b   = blockIdx.x >> 1;     // batch
    const int cid = blockIdx.x & 1;      // 0 = first half, 1 = second half
    const int tbase  = cid ? (HALF - WARM) : 0;
    const int tcount = cid ? (TLEN - tbase) : (HALF + 1);
    const int t0     = cid ? (HALF - WARM + 1) : 1;

    // ---- prologue: B into smem ----
    for (int i = tid; i < EMITN * NS; i += NT) Bsh[i] = Bmat[i];

    // ---- prologue: one-hot -> obs index, own window only ----
    {
        const float* xin = inputs + (size_t)b * TLEN * EMITN;
        for (int tt = tid; tt < tcount; tt += NT) {
            const float4* r = (const float4*)(xin + (size_t)(tbase + tt) * EMITN);
            float idx = 0.0f;
            #pragma unroll
            for (int j = 0; j < 16; j++) {
                float4 v = r[j];
                idx = fmaf((float)(4 * j + 0), v.x, idx);
                idx = fmaf((float)(4 * j + 1), v.y, idx);
                idx = fmaf((float)(4 * j + 2), v.z, idx);
                idx = fmaf((float)(4 * j + 3), v.w, idx);
            }
            obs_sm[tt] = (unsigned char)__float2int_rn(idx);
        }
    }

    // ---- prologue: A block [32w..32w+32) x {4*lane..4*lane+3} ----
    unsigned long long Ar[64];
    if (isCompute) {
        #pragma unroll
        for (int j = 0; j < 4; j++) {
            const int sj = 4 * lane + j;
            #pragma unroll
            for (int i = 0; i < 8; i++) {
                const int k0 = 32 * w + 4 * i;
                Ar[16 * j + 2 * i]     = pk(Amat[(k0 + 0) * NS + sj], Amat[(k0 + 1) * NS + sj]);
                Ar[16 * j + 2 * i + 1] = pk(Amat[(k0 + 2) * NS + sj], Amat[(k0 + 3) * NS + sj]);
            }
        }
    }
    float Ival = isCompute ? Ivec[s] : 0.0f;
    __syncthreads();

    // ---- seed: part[(t0-1)&1] = init "R", sc=1, ubuf[t0&1]=uniform, zs1=Z:1 ----
    const int sb = (t0 - 1) & 1;
    if (isCompute) {
        part[sb][0][s] = cid ? 0.0078125f : Ival;   // combine at t0 gives E∘I / E∘uniform
        part[sb][1][s] = 0.0f;
        part[sb][2][s] = 0.0f;
        part[sb][3][s] = 0.0f;
        ubuf[t0 & 1][s] = 0.0078125f;               // relay's first read: Z = 1
    } else {
        if (lane < 8) { zs1[0][lane] = 0.125f; zs1[1][lane] = 0.125f; }
        if (lane == 0) { sc_sm[0] = 1.0f; sc_sm[1] = 1.0f; }
    }
    __syncthreads();

    int Stot = 0;                                   // valid on tid==128 (relay lane 0)

    if (cid == 0) {
        // ======== chunk 1: exact forward, iterations 1..HALF ========
        run_steps(1, HALF, tbase, isCompute, w, lane, qs, Ar, Bsh, obs_sm,
                  ubuf, part, zs1, sc_sm, Stot);

        // epilogue-combine v_HALF per state, reduce, L1
        if (tid == 128) stot_sm = Stot;
        __syncthreads();
        if (isCompute) {
            const int fb = HALF & 1;
            float scf = sc_sm[fb];
            int o = obs_sm[HALF];
            float E = Bsh[o * NS + s];
            float R = (part[fb][0][s] + part[fb][1][s]) + (part[fb][2][s] + part[fb][3][s]);
            float vv = (E * scf) * R;
            #pragma unroll
            for (int off = 16; off > 0; off >>= 1) vv += __shfl_xor_sync(0xffffffffu, vv, off);
            if (lane == 0) zvs[w] = vv;
        }
        __syncthreads();
        if (tid == 0) {
            float4 zv = *(const float4*)zvs;
            float SV = (zv.x + zv.y) + (zv.z + zv.w);
            g_L1[b] = log((double)SV) + (double)stot_sm * 0.6931471805599453;
        }
    } else {
        // ======== chunk 2: warmup iterations t0..HALF ========
        run_steps(t0, HALF, tbase, isCompute, w, lane, qs, Ar, Bsh, obs_sm,
                  ubuf, part, zs1, sc_sm, Stot);

        // snapshot: log sum v_HALF (same combine the loop will redo at HALF+1)
        if (tid == 128) stot_sm = Stot;
        __syncthreads();
        if (isCompute) {
            const int fb = HALF & 1;
            float scf = sc_sm[fb];
            int o = obs_sm[HALF - tbase];
            float E = Bsh[o * NS + s];
            float R = (part[fb][0][s] + part[fb][1][s]) + (part[fb][2][s] + part[fb][3][s]);
            float vv = (E * scf) * R;
            #pragma unroll
            for (int off = 16; off > 0; off >>= 1) vv += __shfl_xor_sync(0xffffffffu, vv, off);
            if (lane == 0) zvs[w] = vv;
        }
        __syncthreads();
        if (tid == 0) {
            float4 zv = *(const float4*)zvs;
            float SV = (zv.x + zv.y) + (zv.z + zv.w);
            snapL = log((double)SV) + (double)stot_sm * 0.6931471805599453;
        }
        __syncthreads();

        // ======== chunk 2 main: iterations HALF+1 .. TLEN-1 ========
        run_steps(HALF + 1, TLEN - 1, tbase, isCompute, w, lane, qs, Ar, Bsh, obs_sm,
                  ubuf, part, zs1, sc_sm, Stot);

        // final epilogue: alpha_f + L2
        if (tid == 128) stot_sm = Stot;
        __syncthreads();
        float E = 0.f, R = 0.f;
        if (isCompute) {
            const int fb = (TLEN - 1) & 1;
            float scf = sc_sm[fb];
            int o = obs_sm[TLEN - 1 - tbase];
            E = Bsh[o * NS + s];
            R = (part[fb][0][s] + part[fb][1][s]) + (part[fb][2][s] + part[fb][3][s]);
            float vv = (E * scf) * R;
            float rr = R;
            #pragma unroll
            for (int off = 16; off > 0; off >>= 1) {
                rr += __shfl_xor_sync(0xffffffffu, rr, off);
                vv += __shfl_xor_sync(0xffffffffu, vv, off);
            }
            if (lane == 0) { znext[w] = rr; zvs[w] = vv; }
        }
        __syncthreads();

        if (isCompute) {
            float4 zn = *(const float4*)znext;
            float SR = (zn.x + zn.y) + (zn.z + zn.w);  // = sum v_{T-2} (A rows sum to 1)
            out[b * NS + s] = E * R / SR;              // alpha_f (pow2+scf cancel)
        }
        if (tid == 0) {
            float4 zv = *(const float4*)zvs;
            float SV = (zv.x + zv.y) + (zv.z + zv.w);  // sum v_{T-1}
            double Lfin = log((double)SV) + (double)stot_sm * 0.6931471805599453;
            g_L2[b] = Lfin - snapL;
        }
    }
}

__global__ void ll_combine_kernel(float* __restrict__ out)
{
    int b = threadIdx.x;
    out[BATCH * NS + b] = (float)(g_L1[b] + g_L2[b]);
}

extern "C" void kernel_launch(void* const* d_in, const int* in_sizes, int n_in,
                              void* d_out, int out_size)
{
    const float* inputs = (const float*)d_in[0];   // [128, 8192, 64]
    const float* Ivec   = (const float*)d_in[1];   // [128]
    const float* Amat   = (const float*)d_in[2];   // [128, 128]
    const float* Bmat   = (const float*)d_in[3];   // [64, 128]
    float* out = (float*)d_out;                    // alpha_f [128,128] ++ loglik [128]

    hmm_chunk_kernel<<<2 * BATCH, NT>>>(inputs, Ivec, Amat, Bmat, out);
    ll_combine_kernel<<<1, BATCH>>>(out);
}